// round 8
// baseline (speedup 1.0000x reference)
#include <cuda_runtime.h>
#include <cstdint>

#define N_NODES 50000
#define N_EDGES 800000
#define IN_C    128
#define HID_C   128
#define OUT_C   64
#define BN_EPS  1e-5f

// ---------------- device scratch (static, no allocation) ----------------
__device__ float g_deg[N_NODES];
__device__ float g_dinv[N_NODES];
__device__ float g_h1[N_NODES * HID_C];    // x@W1+b1
__device__ float g_agg1[N_NODES * HID_C];  // spmm1 accum, then BN input
__device__ float g_h2[N_NODES * HID_C];    // post BN+ReLU
__device__ float g_g2[N_NODES * OUT_C];    // h2@W2+b2
__device__ float g_bnsum[HID_C];
__device__ float g_bnsumsq[HID_C];
__device__ float g_scale[HID_C];
__device__ float g_shift[HID_C];

// Explicit global-space vector reduction: red.global.add.v4.f32.
// (atomicAdd(float4*) lowers to a GENERIC-space vector red when the address
// space isn't provable, which traps on sm_103a; cvta + .global is supported.)
__device__ __forceinline__ void red_add_v4_global(float* p, float4 v) {
    asm volatile(
        "red.global.add.v4.f32 [%0], {%1, %2, %3, %4};"
        :: "l"(__cvta_generic_to_global(p)),
           "f"(v.x), "f"(v.y), "f"(v.z), "f"(v.w)
        : "memory");
}

// ---------------- zeroing (accumulators must reset every replay) --------
__global__ void zero_kernel() {
    int idx = blockIdx.x * blockDim.x + threadIdx.x;
    int stride = gridDim.x * blockDim.x;
    const int total4 = (N_NODES * HID_C) / 4;
    float4* a = (float4*)g_agg1;
    float4 z = make_float4(0.f, 0.f, 0.f, 0.f);
    for (int i = idx; i < total4; i += stride) a[i] = z;
    for (int i = idx; i < N_NODES; i += stride) g_deg[i] = 0.f;
    if (idx < HID_C) { g_bnsum[idx] = 0.f; g_bnsumsq[idx] = 0.f; }
}

// ---------------- adjacency normalization --------------------------------
// edge_index is int32 (JAX canonicalizes int64->int32 without x64 mode):
// ei[0..E) = src, ei[E..2E) = dst.
__global__ void degree_kernel(const int* __restrict__ ei) {
    int e = blockIdx.x * blockDim.x + threadIdx.x;
    if (e < N_EDGES) {
        int s = ei[e];
        int d = ei[N_EDGES + e];
        if (s != d) atomicAdd(&g_deg[d], 1.0f);
    }
}

__global__ void dinv_kernel() {
    int i = blockIdx.x * blockDim.x + threadIdx.x;
    if (i < N_NODES) g_dinv[i] = rsqrtf(g_deg[i] + 1.0f);
}

// ---------------- GEMM1: h1 = x @ W1 + b1  (M=50000, K=128, N=128) -------
// CTA: 128 rows x 128 cols, 256 threads, 8x8 register tile.
__global__ __launch_bounds__(256) void gemm1_kernel(
    const float* __restrict__ X, const float* __restrict__ W,
    const float* __restrict__ b)
{
    extern __shared__ float sm[];
    float* As = sm;               // [k][r] transposed: As[k*128 + r]
    float* Bs = sm + 128 * 128;   // [k][c]: Bs[k*128 + c]
    const int t = threadIdx.x;
    const int row0 = blockIdx.x * 128;

    const float4* W4 = (const float4*)W;
    float4* Bs4 = (float4*)Bs;
#pragma unroll
    for (int i = 0; i < 16; i++) {
        int idx = t + i * 256;            // 4096 float4 = 128x128
        Bs4[idx] = W4[idx];
    }
#pragma unroll
    for (int i = 0; i < 16; i++) {
        int idx = t + i * 256;
        int r  = idx >> 5;                // 32 float4 per row
        int kc = (idx & 31) << 2;
        int gr = row0 + r; if (gr >= N_NODES) gr = N_NODES - 1;
        float4 v = *(const float4*)(X + (size_t)gr * IN_C + kc);
        As[(kc + 0) * 128 + r] = v.x;
        As[(kc + 1) * 128 + r] = v.y;
        As[(kc + 2) * 128 + r] = v.z;
        As[(kc + 3) * 128 + r] = v.w;
    }
    __syncthreads();

    const int tx = t & 15, ty = t >> 4;
    const int rb = ty * 8, cb = tx * 8;

    float acc[8][8];
#pragma unroll
    for (int i = 0; i < 8; i++)
#pragma unroll
        for (int j = 0; j < 8; j++) acc[i][j] = 0.f;

#pragma unroll 4
    for (int k = 0; k < 128; k++) {
        float4 a0 = *(const float4*)(As + k * 128 + rb);
        float4 a1 = *(const float4*)(As + k * 128 + rb + 4);
        float4 w0 = *(const float4*)(Bs + k * 128 + cb);
        float4 w1 = *(const float4*)(Bs + k * 128 + cb + 4);
        float ar[8] = {a0.x, a0.y, a0.z, a0.w, a1.x, a1.y, a1.z, a1.w};
        float wr[8] = {w0.x, w0.y, w0.z, w0.w, w1.x, w1.y, w1.z, w1.w};
#pragma unroll
        for (int i = 0; i < 8; i++)
#pragma unroll
            for (int j = 0; j < 8; j++) acc[i][j] += ar[i] * wr[j];
    }

    float4 bv0 = *(const float4*)(b + cb);
    float4 bv1 = *(const float4*)(b + cb + 4);
    float bb[8] = {bv0.x, bv0.y, bv0.z, bv0.w, bv1.x, bv1.y, bv1.z, bv1.w};
#pragma unroll
    for (int i = 0; i < 8; i++) {
        int gr = row0 + rb + i;
        if (gr < N_NODES) {
            float4 o0 = make_float4(acc[i][0] + bb[0], acc[i][1] + bb[1],
                                    acc[i][2] + bb[2], acc[i][3] + bb[3]);
            float4 o1 = make_float4(acc[i][4] + bb[4], acc[i][5] + bb[5],
                                    acc[i][6] + bb[6], acc[i][7] + bb[7]);
            *(float4*)(g_h1 + (size_t)gr * HID_C + cb)     = o0;
            *(float4*)(g_h1 + (size_t)gr * HID_C + cb + 4) = o1;
        }
    }
}

// ---------------- SpMM1: agg1[s] += w * h1[d]  (vector global reds) ------
__global__ void spmm1_kernel(const int* __restrict__ ei) {
    const int total = N_EDGES * (HID_C / 4);   // 25.6M
    int idx = blockIdx.x * blockDim.x + threadIdx.x;
    if (idx >= total) return;
    int e  = idx >> 5;      // HID_C/4 = 32 groups per edge
    int cg = idx & 31;
    int s = ei[e];
    int d = ei[N_EDGES + e];
    if (s == d) return;
    float w = g_dinv[s] * g_dinv[d];
    float4 v = *(const float4*)(g_h1 + (size_t)d * HID_C + (cg << 2));
    float4 r = make_float4(w * v.x, w * v.y, w * v.z, w * v.w);
    red_add_v4_global(g_agg1 + (size_t)s * HID_C + (cg << 2), r);
}

// ---------------- BN stats: add self-loop term + channel sums ------------
__global__ __launch_bounds__(128) void bnstat_kernel() {
    const int c = threadIdx.x;   // 128 channels
    float s = 0.f, sq = 0.f;
    for (int r = blockIdx.x; r < N_NODES; r += gridDim.x) {
        float wi = g_dinv[r]; wi *= wi;
        float t = g_agg1[(size_t)r * HID_C + c] + wi * g_h1[(size_t)r * HID_C + c];
        g_agg1[(size_t)r * HID_C + c] = t;
        s  += t;
        sq += t * t;
    }
    atomicAdd(&g_bnsum[c], s);
    atomicAdd(&g_bnsumsq[c], sq);
}

__global__ void bnfinal_kernel(const float* __restrict__ gamma,
                               const float* __restrict__ beta) {
    int c = threadIdx.x;
    float invn = 1.0f / (float)N_NODES;
    float mean = g_bnsum[c] * invn;
    float var  = g_bnsumsq[c] * invn - mean * mean;
    float sc = gamma[c] * rsqrtf(var + BN_EPS);
    g_scale[c] = sc;
    g_shift[c] = beta[c] - mean * sc;
}

// ---------------- normalize + ReLU ---------------------------------------
__global__ void normrelu_kernel() {
    const int total4 = N_NODES * HID_C / 4;
    int i = blockIdx.x * blockDim.x + threadIdx.x;
    if (i >= total4) return;
    int cg = i & 31;
    float4 v  = ((const float4*)g_agg1)[i];
    float4 sc = ((const float4*)g_scale)[cg];
    float4 sh = ((const float4*)g_shift)[cg];
    float4 o;
    o.x = fmaxf(0.f, v.x * sc.x + sh.x);
    o.y = fmaxf(0.f, v.y * sc.y + sh.y);
    o.z = fmaxf(0.f, v.z * sc.z + sh.z);
    o.w = fmaxf(0.f, v.w * sc.w + sh.w);
    ((float4*)g_h2)[i] = o;
}

// ---------------- GEMM2: g2 = h2 @ W2 + b2 (M=50000, K=128, N=64) --------
// CTA: 128 rows x 64 cols, 256 threads, 8x4 register tile.
__global__ __launch_bounds__(256) void gemm2_kernel(
    const float* __restrict__ W, const float* __restrict__ b)
{
    extern __shared__ float sm[];
    float* As = sm;               // [k][r] transposed
    float* Bs = sm + 128 * 128;   // [k][c]: Bs[k*64 + c]
    const int t = threadIdx.x;
    const int row0 = blockIdx.x * 128;

    const float4* W4 = (const float4*)W;   // 2048 float4
    float4* Bs4 = (float4*)Bs;
#pragma unroll
    for (int i = 0; i < 8; i++) Bs4[t + i * 256] = W4[t + i * 256];
#pragma unroll
    for (int i = 0; i < 16; i++) {
        int idx = t + i * 256;
        int r  = idx >> 5;
        int kc = (idx & 31) << 2;
        int gr = row0 + r; if (gr >= N_NODES) gr = N_NODES - 1;
        float4 v = *(const float4*)(g_h2 + (size_t)gr * HID_C + kc);
        As[(kc + 0) * 128 + r] = v.x;
        As[(kc + 1) * 128 + r] = v.y;
        As[(kc + 2) * 128 + r] = v.z;
        As[(kc + 3) * 128 + r] = v.w;
    }
    __syncthreads();

    const int tx = t & 15, ty = t >> 4;
    const int rb = ty * 8, cb = tx * 4;

    float acc[8][4];
#pragma unroll
    for (int i = 0; i < 8; i++)
#pragma unroll
        for (int j = 0; j < 4; j++) acc[i][j] = 0.f;

#pragma unroll 4
    for (int k = 0; k < 128; k++) {
        float4 a0 = *(const float4*)(As + k * 128 + rb);
        float4 a1 = *(const float4*)(As + k * 128 + rb + 4);
        float4 w0 = *(const float4*)(Bs + k * 64 + cb);
        float ar[8] = {a0.x, a0.y, a0.z, a0.w, a1.x, a1.y, a1.z, a1.w};
        float wr[4] = {w0.x, w0.y, w0.z, w0.w};
#pragma unroll
        for (int i = 0; i < 8; i++)
#pragma unroll
            for (int j = 0; j < 4; j++) acc[i][j] += ar[i] * wr[j];
    }

    float4 bv = *(const float4*)(b + cb);
    float bb[4] = {bv.x, bv.y, bv.z, bv.w};
#pragma unroll
    for (int i = 0; i < 8; i++) {
        int gr = row0 + rb + i;
        if (gr < N_NODES) {
            float4 o = make_float4(acc[i][0] + bb[0], acc[i][1] + bb[1],
                                   acc[i][2] + bb[2], acc[i][3] + bb[3]);
            *(float4*)(g_g2 + (size_t)gr * OUT_C + cb) = o;
        }
    }
}

// ---------------- out init with self-loop term ---------------------------
__global__ void selfinit_kernel(float* __restrict__ out) {
    const int total4 = N_NODES * OUT_C / 4;
    int i = blockIdx.x * blockDim.x + threadIdx.x;
    if (i >= total4) return;
    int r = i >> 4;     // 16 float4 per row
    float w = g_dinv[r]; w *= w;
    float4 v = ((const float4*)g_g2)[i];
    ((float4*)out)[i] = make_float4(w * v.x, w * v.y, w * v.z, w * v.w);
}

// ---------------- SpMM2: out[s] += w * g2[d] ------------------------------
__global__ void spmm2_kernel(const int* __restrict__ ei,
                             float* __restrict__ out) {
    const int total = N_EDGES * (OUT_C / 4);   // 12.8M
    int idx = blockIdx.x * blockDim.x + threadIdx.x;
    if (idx >= total) return;
    int e  = idx >> 4;      // OUT_C/4 = 16 groups per edge
    int cg = idx & 15;
    int s = ei[e];
    int d = ei[N_EDGES + e];
    if (s == d) return;
    float w = g_dinv[s] * g_dinv[d];
    float4 v = *(const float4*)(g_g2 + (size_t)d * OUT_C + (cg << 2));
    float4 r = make_float4(w * v.x, w * v.y, w * v.z, w * v.w);
    red_add_v4_global(out + (size_t)s * OUT_C + (cg << 2), r);
}

// ---------------- launcher ------------------------------------------------
extern "C" void kernel_launch(void* const* d_in, const int* in_sizes, int n_in,
                              void* d_out, int out_size) {
    const float* x     = (const float*)d_in[0];
    const int*   ei    = (const int*)d_in[1];
    const float* W1    = (const float*)d_in[2];
    const float* b1    = (const float*)d_in[3];
    const float* gamma = (const float*)d_in[4];
    const float* beta  = (const float*)d_in[5];
    const float* W2    = (const float*)d_in[6];
    const float* b2    = (const float*)d_in[7];
    float* out = (float*)d_out;

    cudaFuncSetAttribute(gemm1_kernel,
        cudaFuncAttributeMaxDynamicSharedMemorySize, 131072);
    cudaFuncSetAttribute(gemm2_kernel,
        cudaFuncAttributeMaxDynamicSharedMemorySize, 98304);

    zero_kernel<<<2048, 256>>>();
    degree_kernel<<<(N_EDGES + 255) / 256, 256>>>(ei);
    dinv_kernel<<<(N_NODES + 255) / 256, 256>>>();

    gemm1_kernel<<<(N_NODES + 127) / 128, 256, 131072>>>(x, W1, b1);
    spmm1_kernel<<<(N_EDGES * (HID_C / 4) + 255) / 256, 256>>>(ei);

    bnstat_kernel<<<1024, 128>>>();
    bnfinal_kernel<<<1, 128>>>(gamma, beta);
    normrelu_kernel<<<(N_NODES * HID_C / 4 + 255) / 256, 256>>>();

    gemm2_kernel<<<(N_NODES + 127) / 128, 256, 98304>>>(W2, b2);
    selfinit_kernel<<<(N_NODES * OUT_C / 4 + 255) / 256, 256>>>(out);
    spmm2_kernel<<<(N_EDGES * (OUT_C / 4) + 255) / 256, 256>>>(ei, out);
}

// round 9
// speedup vs baseline: 1.0055x; 1.0055x over previous
#include <cuda_runtime.h>
#include <cstdint>

#define N_NODES 50000
#define N_EDGES 800000
#define IN_C    128
#define HID_C   128
#define OUT_C   64
#define BN_EPS  1e-5f

// ---------------- device scratch (static, no allocation) ----------------
__device__ float g_deg[N_NODES];
__device__ float g_dinv[N_NODES];
__device__ float g_h1[N_NODES * HID_C];    // x@W1+b1
__device__ float g_agg1[N_NODES * HID_C];  // spmm1 accum, then BN input
__device__ float g_h2[N_NODES * HID_C];    // post BN+ReLU
__device__ float g_g2[N_NODES * OUT_C];    // h2@W2+b2
__device__ float g_bnsum[HID_C];
__device__ float g_bnsumsq[HID_C];
__device__ float g_scale[HID_C];
__device__ float g_shift[HID_C];

// Explicit global-space vector reduction: red.global.add.v4.f32.
// (atomicAdd(float4*) lowers to a GENERIC-space vector red when the address
// space isn't provable, which traps on sm_103a; cvta + .global is supported.)
__device__ __forceinline__ void red_add_v4_global(float* p, float4 v) {
    asm volatile(
        "red.global.add.v4.f32 [%0], {%1, %2, %3, %4};"
        :: "l"(__cvta_generic_to_global(p)),
           "f"(v.x), "f"(v.y), "f"(v.z), "f"(v.w)
        : "memory");
}

// ---------------- zeroing (accumulators must reset every replay) --------
__global__ void zero_kernel() {
    int idx = blockIdx.x * blockDim.x + threadIdx.x;
    int stride = gridDim.x * blockDim.x;
    const int total4 = (N_NODES * HID_C) / 4;
    float4* a = (float4*)g_agg1;
    float4 z = make_float4(0.f, 0.f, 0.f, 0.f);
    for (int i = idx; i < total4; i += stride) a[i] = z;
    for (int i = idx; i < N_NODES; i += stride) g_deg[i] = 0.f;
    if (idx < HID_C) { g_bnsum[idx] = 0.f; g_bnsumsq[idx] = 0.f; }
}

// ---------------- adjacency normalization --------------------------------
// edge_index is int32 (JAX canonicalizes int64->int32 without x64 mode):
// ei[0..E) = src, ei[E..2E) = dst.
__global__ void degree_kernel(const int* __restrict__ ei) {
    int e = blockIdx.x * blockDim.x + threadIdx.x;
    if (e < N_EDGES) {
        int s = ei[e];
        int d = ei[N_EDGES + e];
        if (s != d) atomicAdd(&g_deg[d], 1.0f);
    }
}

__global__ void dinv_kernel() {
    int i = blockIdx.x * blockDim.x + threadIdx.x;
    if (i < N_NODES) g_dinv[i] = rsqrtf(g_deg[i] + 1.0f);
}

// ---------------- GEMM1: h1 = x @ W1 + b1  (M=50000, K=128, N=128) -------
// CTA: 128 rows x 128 cols, 256 threads, 8x8 register tile.
__global__ __launch_bounds__(256) void gemm1_kernel(
    const float* __restrict__ X, const float* __restrict__ W,
    const float* __restrict__ b)
{
    extern __shared__ float sm[];
    float* As = sm;               // [k][r] transposed: As[k*128 + r]
    float* Bs = sm + 128 * 128;   // [k][c]: Bs[k*128 + c]
    const int t = threadIdx.x;
    const int row0 = blockIdx.x * 128;

    const float4* W4 = (const float4*)W;
    float4* Bs4 = (float4*)Bs;
#pragma unroll
    for (int i = 0; i < 16; i++) {
        int idx = t + i * 256;            // 4096 float4 = 128x128
        Bs4[idx] = W4[idx];
    }
#pragma unroll
    for (int i = 0; i < 16; i++) {
        int idx = t + i * 256;
        int r  = idx >> 5;                // 32 float4 per row
        int kc = (idx & 31) << 2;
        int gr = row0 + r; if (gr >= N_NODES) gr = N_NODES - 1;
        float4 v = *(const float4*)(X + (size_t)gr * IN_C + kc);
        As[(kc + 0) * 128 + r] = v.x;
        As[(kc + 1) * 128 + r] = v.y;
        As[(kc + 2) * 128 + r] = v.z;
        As[(kc + 3) * 128 + r] = v.w;
    }
    __syncthreads();

    const int tx = t & 15, ty = t >> 4;
    const int rb = ty * 8, cb = tx * 8;

    float acc[8][8];
#pragma unroll
    for (int i = 0; i < 8; i++)
#pragma unroll
        for (int j = 0; j < 8; j++) acc[i][j] = 0.f;

#pragma unroll 4
    for (int k = 0; k < 128; k++) {
        float4 a0 = *(const float4*)(As + k * 128 + rb);
        float4 a1 = *(const float4*)(As + k * 128 + rb + 4);
        float4 w0 = *(const float4*)(Bs + k * 128 + cb);
        float4 w1 = *(const float4*)(Bs + k * 128 + cb + 4);
        float ar[8] = {a0.x, a0.y, a0.z, a0.w, a1.x, a1.y, a1.z, a1.w};
        float wr[8] = {w0.x, w0.y, w0.z, w0.w, w1.x, w1.y, w1.z, w1.w};
#pragma unroll
        for (int i = 0; i < 8; i++)
#pragma unroll
            for (int j = 0; j < 8; j++) acc[i][j] += ar[i] * wr[j];
    }

    float4 bv0 = *(const float4*)(b + cb);
    float4 bv1 = *(const float4*)(b + cb + 4);
    float bb[8] = {bv0.x, bv0.y, bv0.z, bv0.w, bv1.x, bv1.y, bv1.z, bv1.w};
#pragma unroll
    for (int i = 0; i < 8; i++) {
        int gr = row0 + rb + i;
        if (gr < N_NODES) {
            float4 o0 = make_float4(acc[i][0] + bb[0], acc[i][1] + bb[1],
                                    acc[i][2] + bb[2], acc[i][3] + bb[3]);
            float4 o1 = make_float4(acc[i][4] + bb[4], acc[i][5] + bb[5],
                                    acc[i][6] + bb[6], acc[i][7] + bb[7]);
            *(float4*)(g_h1 + (size_t)gr * HID_C + cb)     = o0;
            *(float4*)(g_h1 + (size_t)gr * HID_C + cb + 4) = o1;
        }
    }
}

// ---------------- SpMM1: agg1[s] += w * h1[d]  (vector global reds) ------
__global__ void spmm1_kernel(const int* __restrict__ ei) {
    const int total = N_EDGES * (HID_C / 4);   // 25.6M
    int idx = blockIdx.x * blockDim.x + threadIdx.x;
    if (idx >= total) return;
    int e  = idx >> 5;      // HID_C/4 = 32 groups per edge
    int cg = idx & 31;
    int s = ei[e];
    int d = ei[N_EDGES + e];
    if (s == d) return;
    float w = g_dinv[s] * g_dinv[d];
    float4 v = *(const float4*)(g_h1 + (size_t)d * HID_C + (cg << 2));
    float4 r = make_float4(w * v.x, w * v.y, w * v.z, w * v.w);
    red_add_v4_global(g_agg1 + (size_t)s * HID_C + (cg << 2), r);
}

// ---------------- BN stats: add self-loop term + channel sums ------------
__global__ __launch_bounds__(128) void bnstat_kernel() {
    const int c = threadIdx.x;   // 128 channels
    float s = 0.f, sq = 0.f;
    for (int r = blockIdx.x; r < N_NODES; r += gridDim.x) {
        float wi = g_dinv[r]; wi *= wi;
        float t = g_agg1[(size_t)r * HID_C + c] + wi * g_h1[(size_t)r * HID_C + c];
        g_agg1[(size_t)r * HID_C + c] = t;
        s  += t;
        sq += t * t;
    }
    atomicAdd(&g_bnsum[c], s);
    atomicAdd(&g_bnsumsq[c], sq);
}

__global__ void bnfinal_kernel(const float* __restrict__ gamma,
                               const float* __restrict__ beta) {
    int c = threadIdx.x;
    float invn = 1.0f / (float)N_NODES;
    float mean = g_bnsum[c] * invn;
    float var  = g_bnsumsq[c] * invn - mean * mean;
    float sc = gamma[c] * rsqrtf(var + BN_EPS);
    g_scale[c] = sc;
    g_shift[c] = beta[c] - mean * sc;
}

// ---------------- normalize + ReLU ---------------------------------------
__global__ void normrelu_kernel() {
    const int total4 = N_NODES * HID_C / 4;
    int i = blockIdx.x * blockDim.x + threadIdx.x;
    if (i >= total4) return;
    int cg = i & 31;
    float4 v  = ((const float4*)g_agg1)[i];
    float4 sc = ((const float4*)g_scale)[cg];
    float4 sh = ((const float4*)g_shift)[cg];
    float4 o;
    o.x = fmaxf(0.f, v.x * sc.x + sh.x);
    o.y = fmaxf(0.f, v.y * sc.y + sh.y);
    o.z = fmaxf(0.f, v.z * sc.z + sh.z);
    o.w = fmaxf(0.f, v.w * sc.w + sh.w);
    ((float4*)g_h2)[i] = o;
}

// ---------------- GEMM2: g2 = h2 @ W2 + b2 (M=50000, K=128, N=64) --------
// CTA: 128 rows x 64 cols, 256 threads, 8x4 register tile.
__global__ __launch_bounds__(256) void gemm2_kernel(
    const float* __restrict__ W, const float* __restrict__ b)
{
    extern __shared__ float sm[];
    float* As = sm;               // [k][r] transposed
    float* Bs = sm + 128 * 128;   // [k][c]: Bs[k*64 + c]
    const int t = threadIdx.x;
    const int row0 = blockIdx.x * 128;

    const float4* W4 = (const float4*)W;   // 2048 float4
    float4* Bs4 = (float4*)Bs;
#pragma unroll
    for (int i = 0; i < 8; i++) Bs4[t + i * 256] = W4[t + i * 256];
#pragma unroll
    for (int i = 0; i < 16; i++) {
        int idx = t + i * 256;
        int r  = idx >> 5;
        int kc = (idx & 31) << 2;
        int gr = row0 + r; if (gr >= N_NODES) gr = N_NODES - 1;
        float4 v = *(const float4*)(g_h2 + (size_t)gr * HID_C + kc);
        As[(kc + 0) * 128 + r] = v.x;
        As[(kc + 1) * 128 + r] = v.y;
        As[(kc + 2) * 128 + r] = v.z;
        As[(kc + 3) * 128 + r] = v.w;
    }
    __syncthreads();

    const int tx = t & 15, ty = t >> 4;
    const int rb = ty * 8, cb = tx * 4;

    float acc[8][4];
#pragma unroll
    for (int i = 0; i < 8; i++)
#pragma unroll
        for (int j = 0; j < 4; j++) acc[i][j] = 0.f;

#pragma unroll 4
    for (int k = 0; k < 128; k++) {
        float4 a0 = *(const float4*)(As + k * 128 + rb);
        float4 a1 = *(const float4*)(As + k * 128 + rb + 4);
        float4 w0 = *(const float4*)(Bs + k * 64 + cb);
        float ar[8] = {a0.x, a0.y, a0.z, a0.w, a1.x, a1.y, a1.z, a1.w};
        float wr[4] = {w0.x, w0.y, w0.z, w0.w};
#pragma unroll
        for (int i = 0; i < 8; i++)
#pragma unroll
            for (int j = 0; j < 4; j++) acc[i][j] += ar[i] * wr[j];
    }

    float4 bv = *(const float4*)(b + cb);
    float bb[4] = {bv.x, bv.y, bv.z, bv.w};
#pragma unroll
    for (int i = 0; i < 8; i++) {
        int gr = row0 + rb + i;
        if (gr < N_NODES) {
            float4 o = make_float4(acc[i][0] + bb[0], acc[i][1] + bb[1],
                                   acc[i][2] + bb[2], acc[i][3] + bb[3]);
            *(float4*)(g_g2 + (size_t)gr * OUT_C + cb) = o;
        }
    }
}

// ---------------- out init with self-loop term ---------------------------
__global__ void selfinit_kernel(float* __restrict__ out) {
    const int total4 = N_NODES * OUT_C / 4;
    int i = blockIdx.x * blockDim.x + threadIdx.x;
    if (i >= total4) return;
    int r = i >> 4;     // 16 float4 per row
    float w = g_dinv[r]; w *= w;
    float4 v = ((const float4*)g_g2)[i];
    ((float4*)out)[i] = make_float4(w * v.x, w * v.y, w * v.z, w * v.w);
}

// ---------------- SpMM2: out[s] += w * g2[d] ------------------------------
__global__ void spmm2_kernel(const int* __restrict__ ei,
                             float* __restrict__ out) {
    const int total = N_EDGES * (OUT_C / 4);   // 12.8M
    int idx = blockIdx.x * blockDim.x + threadIdx.x;
    if (idx >= total) return;
    int e  = idx >> 4;      // OUT_C/4 = 16 groups per edge
    int cg = idx & 15;
    int s = ei[e];
    int d = ei[N_EDGES + e];
    if (s == d) return;
    float w = g_dinv[s] * g_dinv[d];
    float4 v = *(const float4*)(g_g2 + (size_t)d * OUT_C + (cg << 2));
    float4 r = make_float4(w * v.x, w * v.y, w * v.z, w * v.w);
    red_add_v4_global(out + (size_t)s * OUT_C + (cg << 2), r);
}

// ---------------- launcher ------------------------------------------------
extern "C" void kernel_launch(void* const* d_in, const int* in_sizes, int n_in,
                              void* d_out, int out_size) {
    const float* x     = (const float*)d_in[0];
    const int*   ei    = (const int*)d_in[1];
    const float* W1    = (const float*)d_in[2];
    const float* b1    = (const float*)d_in[3];
    const float* gamma = (const float*)d_in[4];
    const float* beta  = (const float*)d_in[5];
    const float* W2    = (const float*)d_in[6];
    const float* b2    = (const float*)d_in[7];
    float* out = (float*)d_out;

    cudaFuncSetAttribute(gemm1_kernel,
        cudaFuncAttributeMaxDynamicSharedMemorySize, 131072);
    cudaFuncSetAttribute(gemm2_kernel,
        cudaFuncAttributeMaxDynamicSharedMemorySize, 98304);

    zero_kernel<<<2048, 256>>>();
    degree_kernel<<<(N_EDGES + 255) / 256, 256>>>(ei);
    dinv_kernel<<<(N_NODES + 255) / 256, 256>>>();

    gemm1_kernel<<<(N_NODES + 127) / 128, 256, 131072>>>(x, W1, b1);
    spmm1_kernel<<<(N_EDGES * (HID_C / 4) + 255) / 256, 256>>>(ei);

    bnstat_kernel<<<1024, 128>>>();
    bnfinal_kernel<<<1, 128>>>(gamma, beta);
    normrelu_kernel<<<(N_NODES * HID_C / 4 + 255) / 256, 256>>>();

    gemm2_kernel<<<(N_NODES + 127) / 128, 256, 98304>>>(W2, b2);
    selfinit_kernel<<<(N_NODES * OUT_C / 4 + 255) / 256, 256>>>(out);
    spmm2_kernel<<<(N_EDGES * (OUT_C / 4) + 255) / 256, 256>>>(ei, out);
}